// round 2
// baseline (speedup 1.0000x reference)
#include <cuda_runtime.h>
#include <math.h>

#define BATCH 8
#define NN    2048
#define FIN   256
#define FOUT  64
#define LALPHA 0.2f
#define NEG_INF -9e15f

#define TI 32
#define TJ 64
#define PSTRIDE 65   // padded stride for p tile (avoid bank conflicts)

// Scratch (allocation-free rule: __device__ globals)
__device__ float g_Wh[BATCH * NN * FOUT];   // 4 MB
__device__ float g_e1[BATCH * NN];
__device__ float g_e2[BATCH * NN];

// ---------------------------------------------------------------------------
// Kernel A: Wh = h @ W^T  and rank-1 logit factors e1 = Wh.a1, e2 = Wh.a2
// One block per (b,n) row, 64 threads (one per output channel).
// ---------------------------------------------------------------------------
__global__ __launch_bounds__(64) void wh_kernel(const float* __restrict__ h,
                                                const float* __restrict__ W,
                                                const float* __restrict__ a) {
    const int bn  = blockIdx.x;          // b*NN + n
    const int tid = threadIdx.x;         // 0..63 = output channel

    __shared__ float sh[FIN];
    __shared__ float s1[FOUT], s2[FOUT];

    const float* hrow = h + (size_t)bn * FIN;
    for (int k = tid; k < FIN; k += 64) sh[k] = hrow[k];
    __syncthreads();

    const float4* w4 = (const float4*)(W + (size_t)tid * FIN);
    const float4* h4 = (const float4*)sh;
    float acc = 0.f;
#pragma unroll 16
    for (int k = 0; k < FIN / 4; k++) {
        float4 wv = w4[k];
        float4 hv = h4[k];
        acc = fmaf(hv.x, wv.x, acc);
        acc = fmaf(hv.y, wv.y, acc);
        acc = fmaf(hv.z, wv.z, acc);
        acc = fmaf(hv.w, wv.w, acc);
    }
    g_Wh[(size_t)bn * FOUT + tid] = acc;

    s1[tid] = acc * a[tid];
    s2[tid] = acc * a[FOUT + tid];
    __syncthreads();
#pragma unroll
    for (int s = 32; s > 0; s >>= 1) {
        if (tid < s) { s1[tid] += s1[tid + s]; s2[tid] += s2[tid + s]; }
        __syncthreads();
    }
    if (tid == 0) { g_e1[bn] = s1[0]; g_e2[bn] = s2[0]; }
}

// ---------------------------------------------------------------------------
// Kernel B: fused masked softmax(lrelu(e1_i + e2_j)) @ Wh, then ELU.
// Block = (b, 32-row i tile). 256 threads: thread t -> row r=t>>3, colgrp c=t&7
// (owns output cols 8c..8c+7). Online softmax across j tiles of 64.
// ---------------------------------------------------------------------------
__global__ __launch_bounds__(256) void attn_kernel(const int* __restrict__ adj,
                                                   float* __restrict__ out) {
    __shared__ float s_wh[TJ * FOUT];        // 16 KB  Wh tile [j][o]
    __shared__ float s_p[TI * PSTRIDE];      // ~8 KB  softmax weights [r][j]
    __shared__ float s_e2[TJ];
    __shared__ float s_e1[TI];

    const int t  = threadIdx.x;
    const int b  = blockIdx.y;
    const int i0 = blockIdx.x * TI;
    const int r  = t >> 3;
    const int c  = t & 7;

    if (t < TI) s_e1[t] = g_e1[b * NN + i0 + t];

    float acc[8];
#pragma unroll
    for (int u = 0; u < 8; u++) acc[u] = 0.f;
    float m = -3.0e38f;
    float l = 0.f;

    const float4* whsrc_b = (const float4*)(g_Wh + (size_t)b * NN * FOUT);
    const int*    adjrow  = adj + ((size_t)b * NN + i0 + r) * NN + c * 8;

    for (int j0 = 0; j0 < NN; j0 += TJ) {
        __syncthreads();   // protect smem from previous accumulate phase

        // load Wh tile [j0..j0+63][0..63] (contiguous) — 1024 float4 / 256 thr
        {
            const float4* src = whsrc_b + (size_t)j0 * (FOUT / 4);
            float4* dst = (float4*)s_wh;
#pragma unroll
            for (int k = 0; k < 4; k++) dst[t + k * 256] = src[t + k * 256];
        }
        if (t < TJ) s_e2[t] = g_e2[b * NN + j0 + t];
        __syncthreads();

        // compute masked logits for this thread's 8 j's, find tile max
        const float e1r = s_e1[r];
        int4 a0 = *(const int4*)(adjrow + j0);
        int4 a1 = *(const int4*)(adjrow + j0 + 4);
        int msk[8] = {a0.x, a0.y, a0.z, a0.w, a1.x, a1.y, a1.z, a1.w};
        float ev[8];
        float tmax = -3.0e38f;
#pragma unroll
        for (int u = 0; u < 8; u++) {
            float x = e1r + s_e2[c * 8 + u];
            x = (x > 0.f) ? x : LALPHA * x;        // leaky relu
            x = (msk[u] > 0) ? x : NEG_INF;        // adjacency mask
            ev[u] = x;
            tmax = fmaxf(tmax, x);
        }
        // reduce max over the 8 threads owning this row (lane groups of 8)
#pragma unroll
        for (int k = 1; k < 8; k <<= 1)
            tmax = fmaxf(tmax, __shfl_xor_sync(0xffffffffu, tmax, k));

        const float m_new = fmaxf(m, tmax);
        const float scale = __expf(m - m_new);
        l *= scale;
#pragma unroll
        for (int u = 0; u < 8; u++) acc[u] *= scale;
#pragma unroll
        for (int u = 0; u < 8; u++) {
            float p = __expf(ev[u] - m_new);
            s_p[r * PSTRIDE + c * 8 + u] = p;
            l += p;
        }
        m = m_new;
        __syncthreads();

        // accumulate: acc[o] += sum_j p[r][j] * Wh[j][o]
        const float* whp = s_wh + c * 8;
        const float* pp  = s_p + r * PSTRIDE;
#pragma unroll 8
        for (int j = 0; j < TJ; j++) {
            const float pj = pp[j];
            const float4 w0 = *(const float4*)(whp + j * FOUT);
            const float4 w1 = *(const float4*)(whp + j * FOUT + 4);
            acc[0] = fmaf(pj, w0.x, acc[0]);
            acc[1] = fmaf(pj, w0.y, acc[1]);
            acc[2] = fmaf(pj, w0.z, acc[2]);
            acc[3] = fmaf(pj, w0.w, acc[3]);
            acc[4] = fmaf(pj, w1.x, acc[4]);
            acc[5] = fmaf(pj, w1.y, acc[5]);
            acc[6] = fmaf(pj, w1.z, acc[6]);
            acc[7] = fmaf(pj, w1.w, acc[7]);
        }
    }

    // reduce l across the row's 8 threads (same m everywhere, partials add)
#pragma unroll
    for (int k = 1; k < 8; k <<= 1)
        l += __shfl_xor_sync(0xffffffffu, l, k);
    const float inv = 1.f / l;

    float o[8];
#pragma unroll
    for (int u = 0; u < 8; u++) {
        float v = acc[u] * inv;
        o[u] = (v > 0.f) ? v : expm1f(v);   // ELU, alpha=1
    }
    float* dst = out + ((size_t)b * NN + i0 + r) * FOUT + c * 8;
    *(float4*)dst       = make_float4(o[0], o[1], o[2], o[3]);
    *(float4*)(dst + 4) = make_float4(o[4], o[5], o[6], o[7]);
}

// ---------------------------------------------------------------------------
extern "C" void kernel_launch(void* const* d_in, const int* in_sizes, int n_in,
                              void* d_out, int out_size) {
    const float* h   = (const float*)d_in[0];   // [8,2048,256]
    const float* W   = (const float*)d_in[1];   // [64,256]
    const float* a   = (const float*)d_in[2];   // [128,1]
    const int*   adj = (const int*)d_in[3];     // [8,2048,2048]
    float* out = (float*)d_out;                 // [8,2048,64]

    wh_kernel<<<BATCH * NN, 64>>>(h, W, a);
    dim3 grid(NN / TI, BATCH);
    attn_kernel<<<grid, 256>>>(adj, out);
}

// round 3
// speedup vs baseline: 3.2697x; 3.2697x over previous
#include <cuda_runtime.h>
#include <math.h>

#define BATCH 8
#define NN    2048
#define FIN   256
#define FOUT  64
#define LALPHA 0.2f

// ---------------- scratch (__device__ globals per allocation rules) --------
__device__ float g_Wh[BATCH * NN * FOUT];   // 4 MB
__device__ float g_e1[BATCH * NN];
__device__ float g_e2[BATCH * NN];
__device__ float g_e2max[BATCH];

// ---------------- f32x2 packed helpers (sm_103a) ---------------------------
typedef unsigned long long ull;
__device__ __forceinline__ ull pack2(float x, float y) {
    ull r; asm("mov.b64 %0, {%1, %2};" : "=l"(r) : "f"(x), "f"(y)); return r;
}
__device__ __forceinline__ void unpack2(float& x, float& y, ull v) {
    asm("mov.b64 {%0, %1}, %2;" : "=f"(x), "=f"(y) : "l"(v));
}
__device__ __forceinline__ void ffma2(ull& d, ull a, ull b) {
    asm("fma.rn.f32x2 %0, %1, %2, %0;" : "+l"(d) : "l"(a), "l"(b));
}

// ---------------------------------------------------------------------------
// Kernel A: Wh = h @ W^T   (16384 x 64 x 256 GEMM, smem-tiled 64x64, k=32)
// 256 threads: thread tile 4 rows x 4 cols.
// ---------------------------------------------------------------------------
#define AK 32
__global__ __launch_bounds__(256) void wh_gemm(const float* __restrict__ h,
                                               const float* __restrict__ W) {
    __shared__ float shT[AK][68];   // [k][row]  (transposed)
    __shared__ float sWT[AK][68];   // [k][o]
    const int t    = threadIdx.x;
    const int row0 = blockIdx.x * 64;
    const int rg   = t >> 4;        // 16 groups -> rows rg*4..+3
    const int cgA  = t & 15;        // 16 groups -> cols cgA*4..+3

    float acc[4][4];
#pragma unroll
    for (int r = 0; r < 4; r++)
#pragma unroll
        for (int c = 0; c < 4; c++) acc[r][c] = 0.f;

    for (int k0 = 0; k0 < FIN; k0 += AK) {
        __syncthreads();
        int idx = t;
#pragma unroll
        for (int u = 0; u < 2; u++, idx += 256) {
            int r = idx >> 3, kq = idx & 7;
            float4 v = *(const float4*)(h + (size_t)(row0 + r) * FIN + k0 + kq * 4);
            shT[kq * 4 + 0][r] = v.x; shT[kq * 4 + 1][r] = v.y;
            shT[kq * 4 + 2][r] = v.z; shT[kq * 4 + 3][r] = v.w;
        }
        idx = t;
#pragma unroll
        for (int u = 0; u < 2; u++, idx += 256) {
            int o = idx >> 3, kq = idx & 7;
            float4 v = *(const float4*)(W + (size_t)o * FIN + k0 + kq * 4);
            sWT[kq * 4 + 0][o] = v.x; sWT[kq * 4 + 1][o] = v.y;
            sWT[kq * 4 + 2][o] = v.z; sWT[kq * 4 + 3][o] = v.w;
        }
        __syncthreads();

#pragma unroll
        for (int k = 0; k < AK; k++) {
            float4 hv = *(const float4*)&shT[k][rg * 4];
            float4 wv = *(const float4*)&sWT[k][cgA * 4];
            float hr[4] = {hv.x, hv.y, hv.z, hv.w};
            float wc[4] = {wv.x, wv.y, wv.z, wv.w};
#pragma unroll
            for (int r = 0; r < 4; r++)
#pragma unroll
                for (int c = 0; c < 4; c++) acc[r][c] = fmaf(hr[r], wc[c], acc[r][c]);
        }
    }
#pragma unroll
    for (int r = 0; r < 4; r++) {
        float4 v = make_float4(acc[r][0], acc[r][1], acc[r][2], acc[r][3]);
        *(float4*)(g_Wh + (size_t)(row0 + rg * 4 + r) * FOUT + cgA * 4) = v;
    }
}

// ---------------------------------------------------------------------------
// Kernel E: e1 = Wh.a1, e2 = Wh.a2, per-batch max(e2). One block per batch.
// ---------------------------------------------------------------------------
__global__ __launch_bounds__(256) void e_kernel(const float* __restrict__ a) {
    const int b = blockIdx.x, t = threadIdx.x;
    __shared__ float sa1[FOUT], sa2[FOUT];
    __shared__ float smax[256];
    if (t < FOUT) sa1[t] = a[t];
    else if (t < 2 * FOUT) sa2[t - FOUT] = a[t];
    __syncthreads();

    float lmax = -3.0e38f;
    for (int s = 0; s < NN / 256; s++) {
        int row = b * NN + s * 256 + t;
        const float4* wh = (const float4*)(g_Wh + (size_t)row * FOUT);
        float e1 = 0.f, e2 = 0.f;
#pragma unroll
        for (int q = 0; q < 16; q++) {
            float4 v = wh[q];
            e1 = fmaf(v.x, sa1[q*4+0], fmaf(v.y, sa1[q*4+1], fmaf(v.z, sa1[q*4+2], fmaf(v.w, sa1[q*4+3], e1))));
            e2 = fmaf(v.x, sa2[q*4+0], fmaf(v.y, sa2[q*4+1], fmaf(v.z, sa2[q*4+2], fmaf(v.w, sa2[q*4+3], e2))));
        }
        g_e1[row] = e1; g_e2[row] = e2;
        lmax = fmaxf(lmax, e2);
    }
    smax[t] = lmax; __syncthreads();
    for (int s = 128; s > 0; s >>= 1) {
        if (t < s) smax[t] = fmaxf(smax[t], smax[t + s]);
        __syncthreads();
    }
    if (t == 0) g_e2max[b] = smax[0];
}

// ---------------------------------------------------------------------------
// Kernel C: fused masked softmax @ Wh + ELU. Single pass (upper-bound max M).
// Block: (b, 64-row i tile), 128 threads. Thread tile: 4 rows x 8 cols
// (cols split {cg*4..+3, cg*4+32..+35} for conflict-free LDS). f32x2 FMAs.
// ---------------------------------------------------------------------------
#define TI 64
#define TJ 64
__global__ __launch_bounds__(128) void attn_kernel(const int* __restrict__ adj,
                                                   float* __restrict__ out) {
    __shared__ float s_wh[TJ][68];      // 17.4 KB  Wh tile [j][o]
    __shared__ float s_p[TI][72];       // 18.4 KB  p[row][j], j in [0,36)+[36,72)
    __shared__ float s_e2[NN];          // 8 KB     all e2 for this batch
    __shared__ float s_e1[TI], s_M[TI], s_l[TI];

    const int t  = threadIdx.x;
    const int b  = blockIdx.y;
    const int i0 = blockIdx.x * TI;
    const int rg = t >> 3;              // 16 groups -> rows rg*4..+3
    const int cg = t & 7;               // cols {cg*4..+3, cg*4+32..+35}

    if (t < TI) {
        float e1v = g_e1[b * NN + i0 + t];
        s_e1[t] = e1v;
        float x = e1v + g_e2max[b];
        s_M[t] = (x > 0.f) ? x : LALPHA * x;
        s_l[t] = 0.f;
    }
    {
        const float4* src = (const float4*)(g_e2 + (size_t)b * NN);
        float4* dst = (float4*)s_e2;
        for (int u = t; u < NN / 4; u += 128) dst[u] = src[u];
    }

    ull acc[4][4];
#pragma unroll
    for (int r = 0; r < 4; r++)
#pragma unroll
        for (int c = 0; c < 4; c++) acc[r][c] = 0ull;

    const float4* whsrc = (const float4*)(g_Wh + (size_t)b * NN * FOUT);
    const int pr = t >> 4;              // p-phase: 8 row-subgroups
    const int jq = t & 15;              // p-phase: int4 index within row

    for (int j0 = 0; j0 < NN; j0 += TJ) {
        __syncthreads();   // also covers initial s_e1/s_M/s_e2 setup (j0==0)

        // ---- load Wh tile [j0..j0+63][0..63] ----
        {
            const float4* src = whsrc + (size_t)j0 * (FOUT / 4);
#pragma unroll
            for (int u = 0; u < 8; u++) {
                int idx = t + u * 128;
                int jj = idx >> 4, o4 = idx & 15;
                *(float4*)&s_wh[jj][o4 * 4] = src[idx];
            }
        }

        // ---- p phase: rows covered in 8 passes of 8 rows, 16 lanes/row ----
        const int joff = jq * 4 + ((jq >= 8) ? 4 : 0);  // padded second half
#pragma unroll
        for (int s = 0; s < 8; s++) {
            const int r = s * 8 + pr;
            int4 av = *(const int4*)(adj + ((size_t)(b * NN + i0 + r)) * NN + j0 + jq * 4);
            const float e1r = s_e1[r], Mr = s_M[r];
            int msk[4] = {av.x, av.y, av.z, av.w};
            float pq[4];
#pragma unroll
            for (int q = 0; q < 4; q++) {
                float x = e1r + s_e2[j0 + jq * 4 + q];
                x = (x > 0.f) ? x : LALPHA * x;
                pq[q] = (msk[q] > 0) ? __expf(x - Mr) : 0.f;
            }
            *(float4*)&s_p[r][joff] = make_float4(pq[0], pq[1], pq[2], pq[3]);
            float lsum = (pq[0] + pq[1]) + (pq[2] + pq[3]);
#pragma unroll
            for (int k = 8; k >= 1; k >>= 1)
                lsum += __shfl_down_sync(0xffffffffu, lsum, k, 16);
            if (jq == 0) s_l[r] += lsum;
        }
        __syncthreads();

        // ---- accumulate: acc[r][.] += p[r][j] * Wh[j][.]  (f32x2 packed) ----
#pragma unroll
        for (int jb = 0; jb < TJ; jb += 4) {
            const int off = jb + ((jb & 32) ? 4 : 0);
            float4 pv[4];
#pragma unroll
            for (int r = 0; r < 4; r++) pv[r] = *(const float4*)&s_p[rg * 4 + r][off];
#pragma unroll
            for (int jj = 0; jj < 4; jj++) {
                float4 w0 = *(const float4*)&s_wh[jb + jj][cg * 4];
                float4 w1 = *(const float4*)&s_wh[jb + jj][cg * 4 + 32];
                ull wp0 = pack2(w0.x, w0.y), wp1 = pack2(w0.z, w0.w);
                ull wp2 = pack2(w1.x, w1.y), wp3 = pack2(w1.z, w1.w);
#pragma unroll
                for (int r = 0; r < 4; r++) {
                    float pj = (jj == 0) ? pv[r].x : (jj == 1) ? pv[r].y
                             : (jj == 2) ? pv[r].z : pv[r].w;
                    ull pd = pack2(pj, pj);
                    ffma2(acc[r][0], pd, wp0);
                    ffma2(acc[r][1], pd, wp1);
                    ffma2(acc[r][2], pd, wp2);
                    ffma2(acc[r][3], pd, wp3);
                }
            }
        }
    }

    // ---- epilogue: normalize + ELU + store ----
#pragma unroll
    for (int r = 0; r < 4; r++) {
        const int row = rg * 4 + r;
        const float inv = 1.f / s_l[row];
        float o[8];
        unpack2(o[0], o[1], acc[r][0]); unpack2(o[2], o[3], acc[r][1]);
        unpack2(o[4], o[5], acc[r][2]); unpack2(o[6], o[7], acc[r][3]);
#pragma unroll
        for (int u = 0; u < 8; u++) {
            float v = o[u] * inv;
            o[u] = (v > 0.f) ? v : expm1f(v);
        }
        float* dst = out + ((size_t)(b * NN + i0 + row)) * FOUT;
        *(float4*)(dst + cg * 4)      = make_float4(o[0], o[1], o[2], o[3]);
        *(float4*)(dst + cg * 4 + 32) = make_float4(o[4], o[5], o[6], o[7]);
    }
}

// ---------------------------------------------------------------------------
extern "C" void kernel_launch(void* const* d_in, const int* in_sizes, int n_in,
                              void* d_out, int out_size) {
    const float* h   = (const float*)d_in[0];   // [8,2048,256]
    const float* W   = (const float*)d_in[1];   // [64,256]
    const float* a   = (const float*)d_in[2];   // [128,1]
    const int*   adj = (const int*)d_in[3];     // [8,2048,2048]
    float* out = (float*)d_out;                 // [8,2048,64]

    wh_gemm<<<BATCH * NN / 64, 256>>>(h, W);
    e_kernel<<<BATCH, 256>>>(a);
    dim3 grid(NN / TI, BATCH);
    attn_kernel<<<grid, 128>>>(adj, out);
}

// round 6
// speedup vs baseline: 5.0124x; 1.5330x over previous
#include <cuda_runtime.h>
#include <cuda_fp16.h>
#include <math.h>
#include <stdint.h>

#define BATCH 8
#define NN    2048
#define FIN   256
#define FOUT  64
#define LALPHA 0.2f

// ---------------- scratch (__device__ globals) -----------------------------
__device__ float  g_Wh[BATCH * NN * FOUT];      // 4 MB fp32 (for e-factors)
__device__ __half g_Whh[BATCH * NN * FOUT];     // 2 MB  [b][j][o] hi
__device__ __half g_Whl[BATCH * NN * FOUT];     // 2 MB  [b][j][o] lo
__device__ float  g_e1[BATCH * NN];
__device__ float  g_e2[BATCH * NN];
__device__ float  g_pmax[64];

// ---------------- PTX helpers ----------------------------------------------
__device__ __forceinline__ uint32_t smem_u32(const void* p) {
    uint32_t a;
    asm("{ .reg .u64 t; cvta.to.shared.u64 t, %1; cvt.u32.u64 %0, t; }" : "=r"(a) : "l"(p));
    return a;
}
__device__ __forceinline__ void ldsm_x4(uint32_t* r, uint32_t a) {
    asm volatile("ldmatrix.sync.aligned.m8n8.x4.shared.b16 {%0,%1,%2,%3}, [%4];"
                 : "=r"(r[0]), "=r"(r[1]), "=r"(r[2]), "=r"(r[3]) : "r"(a));
}
__device__ __forceinline__ void ldsm_x4_t(uint32_t* r, uint32_t a) {
    asm volatile("ldmatrix.sync.aligned.m8n8.x4.trans.shared.b16 {%0,%1,%2,%3}, [%4];"
                 : "=r"(r[0]), "=r"(r[1]), "=r"(r[2]), "=r"(r[3]) : "r"(a));
}
__device__ __forceinline__ void mma16816(float* c, const uint32_t* a,
                                         uint32_t b0, uint32_t b1) {
    asm volatile("mma.sync.aligned.m16n8k16.row.col.f32.f16.f16.f32 "
                 "{%0,%1,%2,%3}, {%4,%5,%6,%7}, {%8,%9}, {%0,%1,%2,%3};"
                 : "+f"(c[0]), "+f"(c[1]), "+f"(c[2]), "+f"(c[3])
                 : "r"(a[0]), "r"(a[1]), "r"(a[2]), "r"(a[3]), "r"(b0), "r"(b1));
}

// ---------------------------------------------------------------------------
// Kernel A: Wh = h @ W^T  (16384x64x256). 32-row tiles, 128 threads, grid 512.
// Epilogue writes fp32 Wh + split-fp16 hi/lo in natural [row][o] layout.
// ---------------------------------------------------------------------------
#define AK 32
__global__ __launch_bounds__(128) void wh_gemm(const float* __restrict__ h,
                                               const float* __restrict__ W) {
    __shared__ float shT[AK][36];   // [k][row]
    __shared__ float sWT[AK][68];   // [k][o]
    const int t    = threadIdx.x;
    const int row0 = blockIdx.x * 32;
    const int rg   = t >> 4;
    const int cgA  = t & 15;

    float acc[4][4];
#pragma unroll
    for (int r = 0; r < 4; r++)
#pragma unroll
        for (int c = 0; c < 4; c++) acc[r][c] = 0.f;

    for (int k0 = 0; k0 < FIN; k0 += AK) {
        __syncthreads();
        {
            int idx = t;
#pragma unroll
            for (int u = 0; u < 2; u++, idx += 128) {
                int r = idx >> 3, kq = idx & 7;
                float4 v = *(const float4*)(h + (size_t)(row0 + r) * FIN + k0 + kq * 4);
                shT[kq*4+0][r] = v.x; shT[kq*4+1][r] = v.y;
                shT[kq*4+2][r] = v.z; shT[kq*4+3][r] = v.w;
            }
            idx = t;
#pragma unroll
            for (int u = 0; u < 4; u++, idx += 128) {
                int o = idx >> 3, kq = idx & 7;
                float4 v = *(const float4*)(W + (size_t)o * FIN + k0 + kq * 4);
                sWT[kq*4+0][o] = v.x; sWT[kq*4+1][o] = v.y;
                sWT[kq*4+2][o] = v.z; sWT[kq*4+3][o] = v.w;
            }
        }
        __syncthreads();
#pragma unroll
        for (int k = 0; k < AK; k++) {
            float4 hv = *(const float4*)&shT[k][rg * 4];
            float4 wv = *(const float4*)&sWT[k][cgA * 4];
            float hr[4] = {hv.x, hv.y, hv.z, hv.w};
            float wc[4] = {wv.x, wv.y, wv.z, wv.w};
#pragma unroll
            for (int r = 0; r < 4; r++)
#pragma unroll
                for (int c = 0; c < 4; c++) acc[r][c] = fmaf(hr[r], wc[c], acc[r][c]);
        }
    }

#pragma unroll
    for (int r = 0; r < 4; r++) {
        const size_t row = row0 + rg * 4 + r;
        *(float4*)(g_Wh + row * FOUT + cgA * 4) =
            make_float4(acc[r][0], acc[r][1], acc[r][2], acc[r][3]);
        // split fp16
        __half2 h01 = __float22half2_rn(make_float2(acc[r][0], acc[r][1]));
        __half2 h23 = __float22half2_rn(make_float2(acc[r][2], acc[r][3]));
        float2 f01 = __half22float2(h01);
        float2 f23 = __half22float2(h23);
        __half2 l01 = __float22half2_rn(make_float2(acc[r][0]-f01.x, acc[r][1]-f01.y));
        __half2 l23 = __float22half2_rn(make_float2(acc[r][2]-f23.x, acc[r][3]-f23.y));
        *(uint2*)(g_Whh + row * FOUT + cgA * 4) = make_uint2(*(unsigned*)&h01, *(unsigned*)&h23);
        *(uint2*)(g_Whl + row * FOUT + cgA * 4) = make_uint2(*(unsigned*)&l01, *(unsigned*)&l23);
    }
}

// ---------------------------------------------------------------------------
// Kernel E: e1/e2 + partial max(e2). 64 blocks, 256 threads.
// ---------------------------------------------------------------------------
__global__ __launch_bounds__(256) void e_kernel(const float* __restrict__ a) {
    const int blk = blockIdx.x, t = threadIdx.x;
    const int bb = blk >> 3, ch = blk & 7;
    __shared__ float sa1[FOUT], sa2[FOUT], smax[256];
    if (t < FOUT) sa1[t] = a[t];
    else if (t < 2 * FOUT) sa2[t - FOUT] = a[t];
    __syncthreads();

    const int row = bb * NN + ch * 256 + t;
    const float4* wh = (const float4*)(g_Wh + (size_t)row * FOUT);
    float e1 = 0.f, e2 = 0.f;
#pragma unroll
    for (int q = 0; q < 16; q++) {
        float4 v = wh[q];
        e1 = fmaf(v.x, sa1[q*4+0], fmaf(v.y, sa1[q*4+1], fmaf(v.z, sa1[q*4+2], fmaf(v.w, sa1[q*4+3], e1))));
        e2 = fmaf(v.x, sa2[q*4+0], fmaf(v.y, sa2[q*4+1], fmaf(v.z, sa2[q*4+2], fmaf(v.w, sa2[q*4+3], e2))));
    }
    g_e1[row] = e1; g_e2[row] = e2;
    smax[t] = e2; __syncthreads();
    for (int s = 128; s > 0; s >>= 1) {
        if (t < s) smax[t] = fmaxf(smax[t], smax[t + s]);
        __syncthreads();
    }
    if (t == 0) g_pmax[blk] = smax[0];
}

// ---------------------------------------------------------------------------
// Kernel C: fused masked softmax @ Wh via mma.sync (split-fp16, 3 terms).
// Block = (b, 128-row tile): grid 128, 256 thr (8 warps, 16 rows/warp).
// ---------------------------------------------------------------------------
// dynamic smem layout (bytes); P/Wh tiles use padded stride 72 halves (144 B)
#define PH_OFF  0
#define PL_OFF  18432
#define WHH_OFF 36864
#define WHL_OFF 46080
#define E2_OFF  55296
#define L_OFF   63488
#define SMEM_SZ 64000

__global__ __launch_bounds__(256) void attn_mma(const int* __restrict__ adj,
                                                float* __restrict__ out) {
    extern __shared__ char smem[];
    const uint32_t sb = smem_u32(smem);

    const int t    = threadIdx.x;
    const int wid  = t >> 5;
    const int lane = t & 31;
    const int b    = blockIdx.y;
    const int i0   = blockIdx.x * 128;

    // P-phase mapping: row = wid*16 + lane/2, half = lane&1 (32 j each)
    const int prow = wid * 16 + (lane >> 1);
    const int half = lane & 1;

    {   // e2 of this batch -> smem
        const float4* src = (const float4*)(g_e2 + (size_t)b * NN);
        float4* dst = (float4*)(smem + E2_OFF);
        for (int u = t; u < NN / 4; u += 256) dst[u] = src[u];
    }
    const float e1r = g_e1[b * NN + i0 + prow];
    float e2m = -3.0e38f;
#pragma unroll
    for (int k = 0; k < 8; k++) e2m = fmaxf(e2m, g_pmax[b * 8 + k]);
    float Mr = e1r + e2m;
    Mr = (Mr > 0.f) ? Mr : LALPHA * Mr;

    const int4* adjp4 = (const int4*)(adj + ((size_t)(b * NN + i0 + prow)) * NN + half * 32);
    int4 abuf[8];
#pragma unroll
    for (int u = 0; u < 8; u++) abuf[u] = adjp4[u];     // tile 0 prefetch

    float acc[8][4];
#pragma unroll
    for (int g = 0; g < 8; g++)
#pragma unroll
        for (int q = 0; q < 4; q++) acc[g][q] = 0.f;
    float lpart = 0.f;

    // mma-phase address components
    const int rb = wid * 16;
    const int m  = lane >> 3, r8 = lane & 7;
    const uint32_t a_off = (uint32_t)(((rb + r8 + 8 * (m & 1)) * 72 + 8 * (m >> 1)) * 2);
    const uint32_t b_off = (uint32_t)(((r8 + 8 * (m & 1)) * 72 + 8 * (m >> 1)) * 2);

    const uint32_t p_off = (uint32_t)((prow * 72 + half * 32) * 2);
    const int wjr = t >> 2;               // Wh smem fill: row, 4 threads/row
    const int wjc = (t & 3) * 16;         // 16 halves each

    __syncthreads();

    for (int jt = 0; jt < 32; jt++) {
        const int j0 = jt * 64;

        // ---- P phase: 32 logits per thread, split fp16, store smem ----
        const float4* e2q = (const float4*)(smem + E2_OFF) + ((j0 + half * 32) >> 2);
#pragma unroll
        for (int c = 0; c < 4; c++) {
            int4 a0 = abuf[2*c], a1 = abuf[2*c + 1];
            if (jt < 31) {
                abuf[2*c]     = adjp4[(jt + 1) * 16 + 2*c];
                abuf[2*c + 1] = adjp4[(jt + 1) * 16 + 2*c + 1];
            }
            float4 ea = e2q[2*c], eb = e2q[2*c + 1];
            float ev[8] = {ea.x, ea.y, ea.z, ea.w, eb.x, eb.y, eb.z, eb.w};
            int   mk[8] = {a0.x, a0.y, a0.z, a0.w, a1.x, a1.y, a1.z, a1.w};
            float pq[8];
#pragma unroll
            for (int q = 0; q < 8; q++) {
                float x = e1r + ev[q];
                x = (x > 0.f) ? x : LALPHA * x;
                pq[q] = (mk[q] > 0) ? __expf(x - Mr) : 0.f;
                lpart += pq[q];
            }
            unsigned vh[4], vl[4];
#pragma unroll
            for (int q = 0; q < 4; q++) {
                __half2 hh = __float22half2_rn(make_float2(pq[2*q], pq[2*q+1]));
                float2 fh = __half22float2(hh);
                __half2 ll = __float22half2_rn(make_float2(pq[2*q]-fh.x, pq[2*q+1]-fh.y));
                vh[q] = *(unsigned*)&hh;
                vl[q] = *(unsigned*)&ll;
            }
            *(uint4*)(smem + PH_OFF + p_off + c * 16) = make_uint4(vh[0], vh[1], vh[2], vh[3]);
            *(uint4*)(smem + PL_OFF + p_off + c * 16) = make_uint4(vl[0], vl[1], vl[2], vl[3]);
        }

        // ---- Wh tile (64 j x 64 o, hi+lo) global -> smem ----
        {
            const size_t gsrc = ((size_t)(b * NN) + j0 + wjr) * FOUT + wjc;
            const uint32_t sdst = (uint32_t)((wjr * 72 + wjc) * 2);
            uint4 h0 = *(const uint4*)(g_Whh + gsrc);
            uint4 h1 = *(const uint4*)(g_Whh + gsrc + 8);
            uint4 l0 = *(const uint4*)(g_Whl + gsrc);
            uint4 l1 = *(const uint4*)(g_Whl + gsrc + 8);
            *(uint4*)(smem + WHH_OFF + sdst)      = h0;
            *(uint4*)(smem + WHH_OFF + sdst + 16) = h1;
            *(uint4*)(smem + WHL_OFF + sdst)      = l0;
            *(uint4*)(smem + WHL_OFF + sdst + 16) = l1;
        }
        __syncthreads();

        // ---- mma phase: 4 k-chunks x 8 n-groups x 3 terms ----
#pragma unroll
        for (int kk = 0; kk < 4; kk++) {
            uint32_t ah[4], al[4];
            ldsm_x4(ah, sb + PH_OFF + a_off + kk * 32);
            ldsm_x4(al, sb + PL_OFF + a_off + kk * 32);
#pragma unroll
            for (int gg = 0; gg < 4; gg++) {
                uint32_t bh[4], bl[4];
                const uint32_t boff = b_off + kk * (16 * 144) + gg * 32;
                ldsm_x4_t(bh, sb + WHH_OFF + boff);
                ldsm_x4_t(bl, sb + WHL_OFF + boff);
                mma16816(acc[2*gg],     ah, bh[0], bh[1]);
                mma16816(acc[2*gg],     ah, bl[0], bl[1]);
                mma16816(acc[2*gg],     al, bh[0], bh[1]);
                mma16816(acc[2*gg + 1], ah, bh[2], bh[3]);
                mma16816(acc[2*gg + 1], ah, bl[2], bl[3]);
                mma16816(acc[2*gg + 1], al, bh[2], bh[3]);
            }
        }
        __syncthreads();
    }

    // ---- denominators ----
    float lsum = lpart + __shfl_xor_sync(0xffffffffu, lpart, 1);
    if (!half) ((float*)(smem + L_OFF))[prow] = lsum;
    __syncthreads();

    // ---- epilogue: normalize + ELU + store ----
    const int row0 = rb + (lane >> 2);
    const int row1 = row0 + 8;
    const float inv0 = 1.f / ((float*)(smem + L_OFF))[row0];
    const float inv1 = 1.f / ((float*)(smem + L_OFF))[row1];
    float* dst0 = out + ((size_t)(b * NN + i0 + row0)) * FOUT + (lane & 3) * 2;
    float* dst1 = out + ((size_t)(b * NN + i0 + row1)) * FOUT + (lane & 3) * 2;
#pragma unroll
    for (int g = 0; g < 8; g++) {
        float v0 = acc[g][0] * inv0, v1 = acc[g][1] * inv0;
        float v2 = acc[g][2] * inv1, v3 = acc[g][3] * inv1;
        v0 = (v0 > 0.f) ? v0 : expm1f(v0);
        v1 = (v1 > 0.f) ? v1 : expm1f(v1);
        v2 = (v2 > 0.f) ? v2 : expm1f(v2);
        v3 = (v3 > 0.f) ? v3 : expm1f(v3);
        *(float2*)(dst0 + g * 8) = make_float2(v0, v1);
        *(float2*)(dst1 + g * 8) = make_float2(v2, v3);
    }
}

// ---------------------------------------------------------------------------
extern "C" void kernel_launch(void* const* d_in, const int* in_sizes, int n_in,
                              void* d_out, int out_size) {
    const float* h   = (const float*)d_in[0];   // [8,2048,256]
    const float* W   = (const float*)d_in[1];   // [64,256]
    const float* a   = (const float*)d_in[2];   // [128,1]
    const int*   adj = (const int*)d_in[3];     // [8,2048,2048]
    float* out = (float*)d_out;                 // [8,2048,64]

    wh_gemm<<<BATCH * NN / 32, 128>>>(h, W);
    e_kernel<<<64, 256>>>(a);
    cudaFuncSetAttribute(attn_mma, cudaFuncAttributeMaxDynamicSharedMemorySize, SMEM_SZ);
    attn_mma<<<dim3(NN / 128, BATCH), 256, SMEM_SZ>>>(adj, out);
}

// round 8
// speedup vs baseline: 5.7728x; 1.1517x over previous
#include <cuda_runtime.h>
#include <cuda_fp16.h>
#include <math.h>
#include <stdint.h>

#define BATCH 8
#define NN    2048
#define FIN   256
#define FOUT  64
#define LALPHA 0.2f

// ---------------- scratch (__device__ globals) -----------------------------
__device__ float  g_Wh[BATCH * NN * FOUT];      // 4 MB fp32 (for e-factors)
__device__ __half g_Whh[BATCH * NN * FOUT];     // 2 MB  [b][j][o] hi
__device__ __half g_Whl[BATCH * NN * FOUT];     // 2 MB  [b][j][o] lo
__device__ float  g_e1[BATCH * NN];
__device__ float  g_e2[BATCH * NN];
__device__ float  g_pmax[64];

// ---------------- PTX helpers ----------------------------------------------
__device__ __forceinline__ uint32_t smem_u32(const void* p) {
    uint32_t a;
    asm("{ .reg .u64 t; cvta.to.shared.u64 t, %1; cvt.u32.u64 %0, t; }" : "=r"(a) : "l"(p));
    return a;
}
__device__ __forceinline__ void ldsm_x4(uint32_t* r, uint32_t a) {
    asm volatile("ldmatrix.sync.aligned.m8n8.x4.shared.b16 {%0,%1,%2,%3}, [%4];"
                 : "=r"(r[0]), "=r"(r[1]), "=r"(r[2]), "=r"(r[3]) : "r"(a));
}
__device__ __forceinline__ void ldsm_x4_t(uint32_t* r, uint32_t a) {
    asm volatile("ldmatrix.sync.aligned.m8n8.x4.trans.shared.b16 {%0,%1,%2,%3}, [%4];"
                 : "=r"(r[0]), "=r"(r[1]), "=r"(r[2]), "=r"(r[3]) : "r"(a));
}
__device__ __forceinline__ void mma16816(float* c, const uint32_t* a,
                                         uint32_t b0, uint32_t b1) {
    asm volatile("mma.sync.aligned.m16n8k16.row.col.f32.f16.f16.f32 "
                 "{%0,%1,%2,%3}, {%4,%5,%6,%7}, {%8,%9}, {%0,%1,%2,%3};"
                 : "+f"(c[0]), "+f"(c[1]), "+f"(c[2]), "+f"(c[3])
                 : "r"(a[0]), "r"(a[1]), "r"(a[2]), "r"(a[3]), "r"(b0), "r"(b1));
}

// ---------------------------------------------------------------------------
// Kernel A: Wh = h @ W^T  (16384x64x256). 64-row tiles, 256 threads, grid 256.
// (validated-fast config) + split-fp16 epilogue in natural [row][o] layout.
// ---------------------------------------------------------------------------
#define AK 32
__global__ __launch_bounds__(256) void wh_gemm(const float* __restrict__ h,
                                               const float* __restrict__ W) {
    __shared__ float shT[AK][68];   // [k][row]
    __shared__ float sWT[AK][68];   // [k][o]
    const int t    = threadIdx.x;
    const int row0 = blockIdx.x * 64;
    const int rg   = t >> 4;        // 16 groups -> rows rg*4..+3
    const int cgA  = t & 15;        // 16 groups -> cols cgA*4..+3

    float acc[4][4];
#pragma unroll
    for (int r = 0; r < 4; r++)
#pragma unroll
        for (int c = 0; c < 4; c++) acc[r][c] = 0.f;

    for (int k0 = 0; k0 < FIN; k0 += AK) {
        __syncthreads();
        int idx = t;
#pragma unroll
        for (int u = 0; u < 2; u++, idx += 256) {
            int r = idx >> 3, kq = idx & 7;
            float4 v = *(const float4*)(h + (size_t)(row0 + r) * FIN + k0 + kq * 4);
            shT[kq*4+0][r] = v.x; shT[kq*4+1][r] = v.y;
            shT[kq*4+2][r] = v.z; shT[kq*4+3][r] = v.w;
        }
        idx = t;
#pragma unroll
        for (int u = 0; u < 2; u++, idx += 256) {
            int o = idx >> 3, kq = idx & 7;
            float4 v = *(const float4*)(W + (size_t)o * FIN + k0 + kq * 4);
            sWT[kq*4+0][o] = v.x; sWT[kq*4+1][o] = v.y;
            sWT[kq*4+2][o] = v.z; sWT[kq*4+3][o] = v.w;
        }
        __syncthreads();

#pragma unroll
        for (int k = 0; k < AK; k++) {
            float4 hv = *(const float4*)&shT[k][rg * 4];
            float4 wv = *(const float4*)&sWT[k][cgA * 4];
            float hr[4] = {hv.x, hv.y, hv.z, hv.w};
            float wc[4] = {wv.x, wv.y, wv.z, wv.w};
#pragma unroll
            for (int r = 0; r < 4; r++)
#pragma unroll
                for (int c = 0; c < 4; c++) acc[r][c] = fmaf(hr[r], wc[c], acc[r][c]);
        }
    }

#pragma unroll
    for (int r = 0; r < 4; r++) {
        const size_t row = row0 + rg * 4 + r;
        *(float4*)(g_Wh + row * FOUT + cgA * 4) =
            make_float4(acc[r][0], acc[r][1], acc[r][2], acc[r][3]);
        __half2 h01 = __float22half2_rn(make_float2(acc[r][0], acc[r][1]));
        __half2 h23 = __float22half2_rn(make_float2(acc[r][2], acc[r][3]));
        float2 f01 = __half22float2(h01);
        float2 f23 = __half22float2(h23);
        __half2 l01 = __float22half2_rn(make_float2(acc[r][0]-f01.x, acc[r][1]-f01.y));
        __half2 l23 = __float22half2_rn(make_float2(acc[r][2]-f23.x, acc[r][3]-f23.y));
        *(uint2*)(g_Whh + row * FOUT + cgA * 4) = make_uint2(*(unsigned*)&h01, *(unsigned*)&h23);
        *(uint2*)(g_Whl + row * FOUT + cgA * 4) = make_uint2(*(unsigned*)&l01, *(unsigned*)&l23);
    }
}

// ---------------------------------------------------------------------------
// Kernel E: e1/e2 + partial max(e2). 64 blocks, 256 threads.
// ---------------------------------------------------------------------------
__global__ __launch_bounds__(256) void e_kernel(const float* __restrict__ a) {
    const int blk = blockIdx.x, t = threadIdx.x;
    const int bb = blk >> 3, ch = blk & 7;
    __shared__ float sa1[FOUT], sa2[FOUT], smax[256];
    if (t < FOUT) sa1[t] = a[t];
    else if (t < 2 * FOUT) sa2[t - FOUT] = a[t];
    __syncthreads();

    const int row = bb * NN + ch * 256 + t;
    const float4* wh = (const float4*)(g_Wh + (size_t)row * FOUT);
    float e1 = 0.f, e2 = 0.f;
#pragma unroll
    for (int q = 0; q < 16; q++) {
        float4 v = wh[q];
        e1 = fmaf(v.x, sa1[q*4+0], fmaf(v.y, sa1[q*4+1], fmaf(v.z, sa1[q*4+2], fmaf(v.w, sa1[q*4+3], e1))));
        e2 = fmaf(v.x, sa2[q*4+0], fmaf(v.y, sa2[q*4+1], fmaf(v.z, sa2[q*4+2], fmaf(v.w, sa2[q*4+3], e2))));
    }
    g_e1[row] = e1; g_e2[row] = e2;
    smax[t] = e2; __syncthreads();
    for (int s = 128; s > 0; s >>= 1) {
        if (t < s) smax[t] = fmaxf(smax[t], smax[t + s]);
        __syncthreads();
    }
    if (t == 0) g_pmax[blk] = smax[0];
}

// ---------------------------------------------------------------------------
// Kernel C: fused masked softmax @ Wh via mma.sync (split-fp16, 3 terms).
// Block = (b, 128-row tile): grid 128, *512* threads (16 warps).
// Warp w: row-slab (w>>1)*16, n-half (w&1)*32. P phase: 4 threads/row, 16 j.
// ---------------------------------------------------------------------------
#define PH_OFF  0
#define PL_OFF  18432
#define WHH_OFF 36864
#define WHL_OFF 46080
#define E2_OFF  55296
#define L_OFF   63488
#define SMEM_SZ 64000

__global__ __launch_bounds__(512) void attn_mma(const int* __restrict__ adj,
                                                float* __restrict__ out) {
    extern __shared__ char smem[];
    const uint32_t sb = smem_u32(smem);

    const int t    = threadIdx.x;
    const int wid  = t >> 5;
    const int lane = t & 31;
    const int b    = blockIdx.y;
    const int i0   = blockIdx.x * 128;

    // P-phase mapping: 4 threads per row, 16 j each
    const int prow = t >> 2;
    const int qtr  = t & 3;

    {   // e2 of this batch -> smem
        const float4* src = (const float4*)(g_e2 + (size_t)b * NN);
        float4* dst = (float4*)(smem + E2_OFF);
        for (int u = t; u < NN / 4; u += 512) dst[u] = src[u];
    }
    const float e1r = g_e1[b * NN + i0 + prow];
    float e2m = -3.0e38f;
#pragma unroll
    for (int k = 0; k < 8; k++) e2m = fmaxf(e2m, g_pmax[b * 8 + k]);
    float Mr = e1r + e2m;
    Mr = (Mr > 0.f) ? Mr : LALPHA * Mr;

    // adj: this thread's 4 int4 (16 ints) per tile
    const int4* adjp4 = (const int4*)(adj + ((size_t)(b * NN + i0 + prow)) * NN) + qtr * 4;
    int4 abuf[4];
#pragma unroll
    for (int u = 0; u < 4; u++) abuf[u] = adjp4[u];      // tile 0 prefetch

    float acc[4][4];
#pragma unroll
    for (int g = 0; g < 4; g++)
#pragma unroll
        for (int q = 0; q < 4; q++) acc[g][q] = 0.f;
    float lpart = 0.f;

    // mma-phase address components
    const int slab  = wid >> 1;           // 0..7 -> 16-row slab
    const int nhalf = wid & 1;            // 0..1 -> 32-col half
    const int rb    = slab * 16;
    const int m  = lane >> 3, r8 = lane & 7;
    const uint32_t a_off = (uint32_t)(((rb + r8 + 8 * (m & 1)) * 72 + 8 * (m >> 1)) * 2);
    const uint32_t b_off = (uint32_t)(((r8 + 8 * (m & 1)) * 72 + 8 * (m >> 1)) * 2);

    const uint32_t p_off = (uint32_t)((prow * 72 + qtr * 16) * 2);
    const int wjr = t >> 3;               // Wh fill: row 0..63
    const int wjc = (t & 7) * 8;          // 8 halves each

    __syncthreads();

    for (int jt = 0; jt < 32; jt++) {
        const int j0 = jt * 64;

        // ---- P phase: 16 logits per thread, split fp16, store smem ----
        const float4* e2q = (const float4*)(smem + E2_OFF) + ((j0 + qtr * 16) >> 2);
        float pq[16];
#pragma unroll
        for (int c = 0; c < 4; c++) {
            int4 av = abuf[c];
            if (jt < 31) abuf[c] = adjp4[(jt + 1) * 16 + c];
            float4 ev = e2q[c];
            float e4[4] = {ev.x, ev.y, ev.z, ev.w};
            int   mk[4] = {av.x, av.y, av.z, av.w};
#pragma unroll
            for (int q = 0; q < 4; q++) {
                float x = e1r + e4[q];
                x = (x > 0.f) ? x : LALPHA * x;
                float p = (mk[q] > 0) ? __expf(x - Mr) : 0.f;
                pq[c * 4 + q] = p;
                lpart += p;
            }
        }
        unsigned vh[8], vl[8];
#pragma unroll
        for (int q = 0; q < 8; q++) {
            __half2 hh = __float22half2_rn(make_float2(pq[2*q], pq[2*q+1]));
            float2 fh = __half22float2(hh);
            __half2 ll = __float22half2_rn(make_float2(pq[2*q]-fh.x, pq[2*q+1]-fh.y));
            vh[q] = *(unsigned*)&hh;
            vl[q] = *(unsigned*)&ll;
        }
        *(uint4*)(smem + PH_OFF + p_off)      = make_uint4(vh[0], vh[1], vh[2], vh[3]);
        *(uint4*)(smem + PH_OFF + p_off + 16) = make_uint4(vh[4], vh[5], vh[6], vh[7]);
        *(uint4*)(smem + PL_OFF + p_off)      = make_uint4(vl[0], vl[1], vl[2], vl[3]);
        *(uint4*)(smem + PL_OFF + p_off + 16) = make_uint4(vl[4], vl[5], vl[6], vl[7]);

        // ---- Wh tile (64 j x 64 o, hi+lo): 1 uint4 per thread each ----
        {
            const size_t gsrc = ((size_t)(b * NN) + j0 + wjr) * FOUT + wjc;
            const uint32_t sdst = (uint32_t)((wjr * 72 + wjc) * 2);
            *(uint4*)(smem + WHH_OFF + sdst) = *(const uint4*)(g_Whh + gsrc);
            *(uint4*)(smem + WHL_OFF + sdst) = *(const uint4*)(g_Whl + gsrc);
        }
        __syncthreads();

        // ---- mma phase: 4 k-chunks x 2 n-groups x 3 terms ----
#pragma unroll
        for (int kk = 0; kk < 4; kk++) {
            uint32_t ah[4], al[4];
            ldsm_x4(ah, sb + PH_OFF + a_off + kk * 32);
            ldsm_x4(al, sb + PL_OFF + a_off + kk * 32);
#pragma unroll
            for (int gg = 0; gg < 2; gg++) {
                uint32_t bh[4], bl[4];
                const uint32_t boff = b_off + kk * (16 * 144) + (nhalf * 2 + gg) * 32;
                ldsm_x4_t(bh, sb + WHH_OFF + boff);
                ldsm_x4_t(bl, sb + WHL_OFF + boff);
                mma16816(acc[2*gg],     ah, bh[0], bh[1]);
                mma16816(acc[2*gg],     ah, bl[0], bl[1]);
                mma16816(acc[2*gg],     al, bh[0], bh[1]);
                mma16816(acc[2*gg + 1], ah, bh[2], bh[3]);
                mma16816(acc[2*gg + 1], ah, bl[2], bl[3]);
                mma16816(acc[2*gg + 1], al, bh[2], bh[3]);
            }
        }
        __syncthreads();
    }

    // ---- denominators: reduce over the 4 threads of each row ----
    lpart += __shfl_xor_sync(0xffffffffu, lpart, 1);
    lpart += __shfl_xor_sync(0xffffffffu, lpart, 2);
    if (qtr == 0) ((float*)(smem + L_OFF))[prow] = lpart;
    __syncthreads();

    // ---- epilogue: normalize + ELU + store ----
    const int row0 = rb + (lane >> 2);
    const int row1 = row0 + 8;
    const float inv0 = 1.f / ((float*)(smem + L_OFF))[row0];
    const float inv1 = 1.f / ((float*)(smem + L_OFF))[row1];
    float* dst0 = out + ((size_t)(b * NN + i0 + row0)) * FOUT + nhalf * 32 + (lane & 3) * 2;
    float* dst1 = out + ((size_t)(b * NN + i0 + row1)) * FOUT + nhalf * 32 + (lane & 3) * 2;
#pragma unroll
    for (int g = 0; g < 4; g++) {
        float v0 = acc[g][0] * inv0, v1 = acc[g][1] * inv0;
        float v2 = acc[g][2] * inv1, v3 = acc[g][3] * inv1;
        v0 = (v0 > 0.f) ? v0 : expm1f(v0);
        v1 = (v1 > 0.f) ? v1 : expm1f(v1);
        v2 = (v2 > 0.f) ? v2 : expm1f(v2);
        v3 = (v3 > 0.f) ? v3 : expm1f(v3);
        *(float2*)(dst0 + g * 8) = make_float2(v0, v1);
        *(float2*)(dst1 + g * 8) = make_float2(v2, v3);
    }
}

// ---------------------------------------------------------------------------
extern "C" void kernel_launch(void* const* d_in, const int* in_sizes, int n_in,
                              void* d_out, int out_size) {
    const float* h   = (const float*)d_in[0];   // [8,2048,256]
    const float* W   = (const float*)d_in[1];   // [64,256]
    const float* a   = (const float*)d_in[2];   // [128,1]
    const int*   adj = (const int*)d_in[3];     // [8,2048,2048]
    float* out = (float*)d_out;                 // [8,2048,64]

    wh_gemm<<<BATCH * NN / 64, 256>>>(h, W);
    e_kernel<<<64, 256>>>(a);
    cudaFuncSetAttribute(attn_mma, cudaFuncAttributeMaxDynamicSharedMemorySize, SMEM_SZ);
    attn_mma<<<dim3(NN / 128, BATCH), 512, SMEM_SZ>>>(adj, out);
}

// round 11
// speedup vs baseline: 6.8263x; 1.1825x over previous
#include <cuda_runtime.h>
#include <cuda_fp16.h>
#include <math.h>
#include <stdint.h>

#define BATCH 8
#define NN    2048
#define FIN   256
#define FOUT  64
#define LALPHA 0.2f

// ---------------- scratch (__device__ globals) -----------------------------
__device__ float  g_Wh[BATCH * NN * FOUT];      // 4 MB fp32 (for e-factors)
__device__ __half g_Whh[BATCH * NN * FOUT];     // 2 MB  [b][j][o] hi
__device__ __half g_Whl[BATCH * NN * FOUT];     // 2 MB  [b][j][o] lo
__device__ float  g_e1[BATCH * NN];
__device__ float2 g_BD[BATCH * NN];             // (exp(e2), exp(0.2*e2))
__device__ float  g_pmax[64];

// ---------------- PTX helpers ----------------------------------------------
__device__ __forceinline__ uint32_t smem_u32(const void* p) {
    uint32_t a;
    asm("{ .reg .u64 t; cvta.to.shared.u64 t, %1; cvt.u32.u64 %0, t; }" : "=r"(a) : "l"(p));
    return a;
}
__device__ __forceinline__ void ldsm_x4(uint32_t* r, uint32_t a) {
    asm volatile("ldmatrix.sync.aligned.m8n8.x4.shared.b16 {%0,%1,%2,%3}, [%4];"
                 : "=r"(r[0]), "=r"(r[1]), "=r"(r[2]), "=r"(r[3]) : "r"(a));
}
__device__ __forceinline__ void ldsm_x4_t(uint32_t* r, uint32_t a) {
    asm volatile("ldmatrix.sync.aligned.m8n8.x4.trans.shared.b16 {%0,%1,%2,%3}, [%4];"
                 : "=r"(r[0]), "=r"(r[1]), "=r"(r[2]), "=r"(r[3]) : "r"(a));
}
__device__ __forceinline__ void mma16816(float* c, const uint32_t* a,
                                         uint32_t b0, uint32_t b1) {
    asm volatile("mma.sync.aligned.m16n8k16.row.col.f32.f16.f16.f32 "
                 "{%0,%1,%2,%3}, {%4,%5,%6,%7}, {%8,%9}, {%0,%1,%2,%3};"
                 : "+f"(c[0]), "+f"(c[1]), "+f"(c[2]), "+f"(c[3])
                 : "r"(a[0]), "r"(a[1]), "r"(a[2]), "r"(a[3]), "r"(b0), "r"(b1));
}

// ---------------------------------------------------------------------------
// Kernel A: Wh = h @ W^T  (16384x64x256). 64-row tiles, 256 threads, grid 256.
// ---------------------------------------------------------------------------
#define AK 32
__global__ __launch_bounds__(256) void wh_gemm(const float* __restrict__ h,
                                               const float* __restrict__ W) {
    __shared__ float shT[AK][68];
    __shared__ float sWT[AK][68];
    const int t    = threadIdx.x;
    const int row0 = blockIdx.x * 64;
    const int rg   = t >> 4;
    const int cgA  = t & 15;

    float acc[4][4];
#pragma unroll
    for (int r = 0; r < 4; r++)
#pragma unroll
        for (int c = 0; c < 4; c++) acc[r][c] = 0.f;

    for (int k0 = 0; k0 < FIN; k0 += AK) {
        __syncthreads();
        int idx = t;
#pragma unroll
        for (int u = 0; u < 2; u++, idx += 256) {
            int r = idx >> 3, kq = idx & 7;
            float4 v = *(const float4*)(h + (size_t)(row0 + r) * FIN + k0 + kq * 4);
            shT[kq*4+0][r] = v.x; shT[kq*4+1][r] = v.y;
            shT[kq*4+2][r] = v.z; shT[kq*4+3][r] = v.w;
        }
        idx = t;
#pragma unroll
        for (int u = 0; u < 2; u++, idx += 256) {
            int o = idx >> 3, kq = idx & 7;
            float4 v = *(const float4*)(W + (size_t)o * FIN + k0 + kq * 4);
            sWT[kq*4+0][o] = v.x; sWT[kq*4+1][o] = v.y;
            sWT[kq*4+2][o] = v.z; sWT[kq*4+3][o] = v.w;
        }
        __syncthreads();

#pragma unroll
        for (int k = 0; k < AK; k++) {
            float4 hv = *(const float4*)&shT[k][rg * 4];
            float4 wv = *(const float4*)&sWT[k][cgA * 4];
            float hr[4] = {hv.x, hv.y, hv.z, hv.w};
            float wc[4] = {wv.x, wv.y, wv.z, wv.w};
#pragma unroll
            for (int r = 0; r < 4; r++)
#pragma unroll
                for (int c = 0; c < 4; c++) acc[r][c] = fmaf(hr[r], wc[c], acc[r][c]);
        }
    }

#pragma unroll
    for (int r = 0; r < 4; r++) {
        const size_t row = row0 + rg * 4 + r;
        *(float4*)(g_Wh + row * FOUT + cgA * 4) =
            make_float4(acc[r][0], acc[r][1], acc[r][2], acc[r][3]);
        __half2 h01 = __float22half2_rn(make_float2(acc[r][0], acc[r][1]));
        __half2 h23 = __float22half2_rn(make_float2(acc[r][2], acc[r][3]));
        float2 f01 = __half22float2(h01);
        float2 f23 = __half22float2(h23);
        __half2 l01 = __float22half2_rn(make_float2(acc[r][0]-f01.x, acc[r][1]-f01.y));
        __half2 l23 = __float22half2_rn(make_float2(acc[r][2]-f23.x, acc[r][3]-f23.y));
        *(uint2*)(g_Whh + row * FOUT + cgA * 4) = make_uint2(*(unsigned*)&h01, *(unsigned*)&h23);
        *(uint2*)(g_Whl + row * FOUT + cgA * 4) = make_uint2(*(unsigned*)&l01, *(unsigned*)&l23);
    }
}

// ---------------------------------------------------------------------------
// Kernel E: e1, (B,D)=exp factors, partial max(e2). 64 blocks, 256 threads.
// ---------------------------------------------------------------------------
__global__ __launch_bounds__(256) void e_kernel(const float* __restrict__ a) {
    const int blk = blockIdx.x, t = threadIdx.x;
    const int bb = blk >> 3, ch = blk & 7;
    __shared__ float sa1[FOUT], sa2[FOUT], smax[256];
    if (t < FOUT) sa1[t] = a[t];
    else if (t < 2 * FOUT) sa2[t - FOUT] = a[t];
    __syncthreads();

    const int row = bb * NN + ch * 256 + t;
    const float4* wh = (const float4*)(g_Wh + (size_t)row * FOUT);
    float e1 = 0.f, e2 = 0.f;
#pragma unroll
    for (int q = 0; q < 16; q++) {
        float4 v = wh[q];
        e1 = fmaf(v.x, sa1[q*4+0], fmaf(v.y, sa1[q*4+1], fmaf(v.z, sa1[q*4+2], fmaf(v.w, sa1[q*4+3], e1))));
        e2 = fmaf(v.x, sa2[q*4+0], fmaf(v.y, sa2[q*4+1], fmaf(v.z, sa2[q*4+2], fmaf(v.w, sa2[q*4+3], e2))));
    }
    g_e1[row] = e1;
    g_BD[row] = make_float2(__expf(e2), __expf(LALPHA * e2));
    smax[t] = e2; __syncthreads();
    for (int s = 128; s > 0; s >>= 1) {
        if (t < s) smax[t] = fmaxf(smax[t], smax[t + s]);
        __syncthreads();
    }
    if (t == 0) g_pmax[blk] = smax[0];
}

// ---------------------------------------------------------------------------
// Kernel C: fused masked softmax @ Wh via mma.sync (P fp16-hi, Wh split, 2 terms).
// NO exp in inner loop: p = adj ? (B_j>T_i ? A_i*B_j : C_i*D_j) : 0.
// Block = (b, 64-row tile): grid (32,8)=256 blocks, 512 thr, 2 blocks/SM.
// Warp w: row-slab (w>>2)*16, n-quarter (w&3)*16. P: 8 thr/row, 8 j each.
// ---------------------------------------------------------------------------
#define PH_OFF  0
#define WHH_OFF 9216
#define WHL_OFF 18432
#define BD_OFF  27648
#define L_OFF   44032
#define SMEM_SZ 44544

__global__ __launch_bounds__(512, 2) void attn_mma(const int* __restrict__ adj,
                                                   float* __restrict__ out) {
    extern __shared__ char smem[];
    const uint32_t sb = smem_u32(smem);

    const int t    = threadIdx.x;
    const int wid  = t >> 5;
    const int lane = t & 31;
    const int b    = blockIdx.y;
    const int i0   = blockIdx.x * 64;

    // P-phase mapping: 8 threads per row, 8 j each
    const int prow = t >> 3;
    const int oct  = t & 7;

    {   // (B,D) factors of this batch -> smem (1024 float4)
        const float4* src = (const float4*)(g_BD + (size_t)b * NN);
        float4* dst = (float4*)(smem + BD_OFF);
#pragma unroll
        for (int u = 0; u < 2; u++) dst[t + u * 512] = src[t + u * 512];
    }
    const float e1r = g_e1[b * NN + i0 + prow];
    float e2m = -3.0e38f;
#pragma unroll
    for (int k = 0; k < 8; k++) e2m = fmaxf(e2m, g_pmax[b * 8 + k]);
    float Mr = e1r + e2m;
    Mr = (Mr > 0.f) ? Mr : LALPHA * Mr;
    const float Ar = __expf(e1r - Mr);
    const float Cr = __expf(LALPHA * e1r - Mr);
    const float Tr = __expf(-e1r);

    // adj: this thread's 2 int4 (8 ints) per tile
    const int4* adjp4 = (const int4*)(adj + ((size_t)(b * NN + i0 + prow)) * NN) + oct * 2;
    int4 abuf[2];
    abuf[0] = adjp4[0]; abuf[1] = adjp4[1];

    float acc[2][4];
#pragma unroll
    for (int g = 0; g < 2; g++)
#pragma unroll
        for (int q = 0; q < 4; q++) acc[g][q] = 0.f;
    float lpart = 0.f;

    // mma-phase address components
    const int slab = wid >> 2;            // 0..3 -> 16-row slab
    const int nq   = wid & 3;             // 0..3 -> 16-col quarter
    const int rb   = slab * 16;
    const int m  = lane >> 3, r8 = lane & 7;
    const uint32_t a_off = (uint32_t)(((rb + r8 + 8 * (m & 1)) * 72 + 8 * (m >> 1)) * 2);
    const uint32_t b_off = (uint32_t)(((r8 + 8 * (m & 1)) * 72 + 8 * (m >> 1)) * 2);

    const uint32_t p_off = (uint32_t)((prow * 72 + oct * 8) * 2);
    const int wjr = t >> 3;               // Wh fill: row 0..63
    const int wjc = (t & 7) * 8;          // 8 halves each

    __syncthreads();

    for (int jt = 0; jt < 32; jt++) {
        const int j0 = jt * 64;

        // ---- P phase: 8 probs per thread (no exp!), fp16-hi, store smem ----
        const float4* bdq = (const float4*)(smem + BD_OFF) + ((j0 + oct * 8) >> 1);
        float pq[8];
#pragma unroll
        for (int c = 0; c < 2; c++) {
            int4 av = abuf[c];
            if (jt < 31) abuf[c] = adjp4[(jt + 1) * 16 + c];
            float4 bd0 = bdq[c * 2];        // (B0, D0, B1, D1)
            float4 bd1 = bdq[c * 2 + 1];    // (B2, D2, B3, D3)
            float Bv[4] = {bd0.x, bd0.z, bd1.x, bd1.z};
            float Dv[4] = {bd0.y, bd0.w, bd1.y, bd1.w};
            int   mk[4] = {av.x, av.y, av.z, av.w};
#pragma unroll
            for (int q = 0; q < 4; q++) {
                bool hi = Bv[q] > Tr;
                float p = (hi ? Ar : Cr) * (hi ? Bv[q] : Dv[q]);
                p = (mk[q] > 0) ? p : 0.f;
                pq[c * 4 + q] = p;
                lpart += p;
            }
        }
        {
            unsigned vh[4];
#pragma unroll
            for (int q = 0; q < 4; q++) {
                __half2 hh = __float22half2_rn(make_float2(pq[2*q], pq[2*q+1]));
                vh[q] = *(unsigned*)&hh;
            }
            *(uint4*)(smem + PH_OFF + p_off) = make_uint4(vh[0], vh[1], vh[2], vh[3]);
        }

        // ---- Wh tile (64 j x 64 o, hi+lo): 1 uint4 per thread each ----
        {
            const size_t gsrc = ((size_t)(b * NN) + j0 + wjr) * FOUT + wjc;
            const uint32_t sdst = (uint32_t)((wjr * 72 + wjc) * 2);
            *(uint4*)(smem + WHH_OFF + sdst) = *(const uint4*)(g_Whh + gsrc);
            *(uint4*)(smem + WHL_OFF + sdst) = *(const uint4*)(g_Whl + gsrc);
        }
        __syncthreads();

        // ---- mma phase: 4 k-chunks x 1 n-quarter x 2 terms ----
#pragma unroll
        for (int kk = 0; kk < 4; kk++) {
            uint32_t ah[4];
            ldsm_x4(ah, sb + PH_OFF + a_off + kk * 32);
            uint32_t bh[4], bl[4];
            const uint32_t boff = b_off + kk * (16 * 144) + nq * 32;
            ldsm_x4_t(bh, sb + WHH_OFF + boff);
            ldsm_x4_t(bl, sb + WHL_OFF + boff);
            mma16816(acc[0], ah, bh[0], bh[1]);
            mma16816(acc[0], ah, bl[0], bl[1]);
            mma16816(acc[1], ah, bh[2], bh[3]);
            mma16816(acc[1], ah, bl[2], bl[3]);
        }
        __syncthreads();
    }

    // ---- denominators: reduce over the 8 threads of each row ----
    lpart += __shfl_xor_sync(0xffffffffu, lpart, 1);
    lpart += __shfl_xor_sync(0xffffffffu, lpart, 2);
    lpart += __shfl_xor_sync(0xffffffffu, lpart, 4);
    if (oct == 0) ((float*)(smem + L_OFF))[prow] = lpart;
    __syncthreads();

    // ---- epilogue: normalize + ELU + store ----
    const int row0 = rb + (lane >> 2);
    const int row1 = row0 + 8;
    const float inv0 = 1.f / ((float*)(smem + L_OFF))[row0];
    const float inv1 = 1.f / ((float*)(smem + L_OFF))[row1];
    const int cbase = nq * 16 + (lane & 3) * 2;
    float* dst0 = out + ((size_t)(b * NN + i0 + row0)) * FOUT + cbase;
    float* dst1 = out + ((size_t)(b * NN + i0 + row1)) * FOUT + cbase;
#pragma unroll
    for (int g = 0; g < 2; g++) {
        float v0 = acc[g][0] * inv0, v1 = acc[g][1] * inv0;
        float v2 = acc[g][2] * inv1, v3 = acc[g][3] * inv1;
        v0 = (v0 > 0.f) ? v0 : expm1f(v0);
        v1 = (v1 > 0.f) ? v1 : expm1f(v1);
        v2 = (v2 > 0.f) ? v2 : expm1f(v2);
        v3 = (v3 > 0.f) ? v3 : expm1f(v3);
        *(float2*)(dst0 + g * 8) = make_float2(v0, v1);
        *(float2*)(dst1 + g * 8) = make_float2(v2, v3);
    }
}

// ---------------------------------------------------------------------------
extern "C" void kernel_launch(void* const* d_in, const int* in_sizes, int n_in,
                              void* d_out, int out_size) {
    const float* h   = (const float*)d_in[0];   // [8,2048,256]
    const float* W   = (const float*)d_in[1];   // [64,256]
    const float* a   = (const float*)d_in[2];   // [128,1]
    const int*   adj = (const int*)d_in[3];     // [8,2048,2048]
    float* out = (float*)d_out;                 // [8,2048,64]

    wh_gemm<<<BATCH * NN / 64, 256>>>(h, W);
    e_kernel<<<64, 256>>>(a);
    cudaFuncSetAttribute(attn_mma, cudaFuncAttributeMaxDynamicSharedMemorySize, SMEM_SZ);
    attn_mma<<<dim3(NN / 64, BATCH), 512, SMEM_SZ>>>(adj, out);
}